// round 4
// baseline (speedup 1.0000x reference)
#include <cuda_runtime.h>
#include <math.h>

// ---------------- problem constants ----------------
#define BB 8
#define SS 384
#define IN_DIM 512
#define EE 512
#define HH 8
#define DD 64
#define BSROWS (BB*SS)        // 3072
#define ND 767                // distinct rel offsets used: j-i+383 in [0,766]
#define LDT 768               // padded leading dim for QPK/KPQ
#define REL_OFF 128           // rel_table row offset: table row = t + 128
#define SCALE_F 0.07216878364870323f   // 1/sqrt(64*3)

// ---------------- scratch (__device__ globals; no runtime allocation) ------
__device__ float g_Q[(size_t)HH*BSROWS*DD];
__device__ float g_K[(size_t)HH*BSROWS*DD];
__device__ float g_V[(size_t)HH*BSROWS*DD];
__device__ float g_PK[(size_t)HH*ND*DD];
__device__ float g_PQ[(size_t)HH*ND*DD];
__device__ float g_QPK[(size_t)HH*BSROWS*LDT];   // ~75 MB
__device__ float g_KPQ[(size_t)HH*BSROWS*LDT];   // ~75 MB
__device__ float g_vals[(size_t)BSROWS*EE];

// ---------------- generic NT SGEMM: C = A(MxK) * B(NxK)^T + bias ----------
// mode 0: C[m*ldc + n]
// mode 1: head-split: h=n>>6, C[h*headM*64 + m*64 + (n&63)]
__global__ __launch_bounds__(256)
void gemm_nt(const float* __restrict__ A, int lda, long sA,
             const float* __restrict__ Bm, int ldb, long sB,
             const float* __restrict__ bias,
             float* __restrict__ C, long sC,
             int M, int N, int K,
             int mode, int ldc, int headM)
{
    int bz = blockIdx.z;
    A  += (long)bz * sA;
    Bm += (long)bz * sB;
    C  += (long)bz * sC;

    __shared__ float As[16][65];   // As[k][m]
    __shared__ float Bs[16][65];   // Bs[k][n]

    int tid = threadIdx.x;
    int m0 = blockIdx.y * 64;
    int n0 = blockIdx.x * 64;
    int tx = tid & 15, ty = tid >> 4;

    float acc[4][4];
#pragma unroll
    for (int i = 0; i < 4; i++)
#pragma unroll
        for (int j = 0; j < 4; j++) acc[i][j] = 0.f;

    int lrow = tid >> 2;          // 0..63
    int lcol = (tid & 3) * 4;     // 0,4,8,12

    for (int k0 = 0; k0 < K; k0 += 16) {
        // load A tile (64 x 16), transposed into As[k][m]
        {
            int m = m0 + lrow;
            float4 v = make_float4(0.f, 0.f, 0.f, 0.f);
            if (m < M) v = *(const float4*)(A + (long)m * lda + k0 + lcol);
            As[lcol + 0][lrow] = v.x;
            As[lcol + 1][lrow] = v.y;
            As[lcol + 2][lrow] = v.z;
            As[lcol + 3][lrow] = v.w;
        }
        // load B tile (64 x 16)
        {
            int n = n0 + lrow;
            float4 v = make_float4(0.f, 0.f, 0.f, 0.f);
            if (n < N) v = *(const float4*)(Bm + (long)n * ldb + k0 + lcol);
            Bs[lcol + 0][lrow] = v.x;
            Bs[lcol + 1][lrow] = v.y;
            Bs[lcol + 2][lrow] = v.z;
            Bs[lcol + 3][lrow] = v.w;
        }
        __syncthreads();
#pragma unroll
        for (int kk = 0; kk < 16; kk++) {
            float a[4], b[4];
#pragma unroll
            for (int i = 0; i < 4; i++) a[i] = As[kk][ty * 4 + i];
#pragma unroll
            for (int j = 0; j < 4; j++) b[j] = Bs[kk][tx * 4 + j];
#pragma unroll
            for (int i = 0; i < 4; i++)
#pragma unroll
                for (int j = 0; j < 4; j++) acc[i][j] += a[i] * b[j];
        }
        __syncthreads();
    }

#pragma unroll
    for (int i = 0; i < 4; i++) {
#pragma unroll
        for (int j = 0; j < 4; j++) {
            int m = m0 + ty * 4 + i;
            int n = n0 + tx * 4 + j;
            if (m < M && n < N) {
                float v = acc[i][j] + (bias ? bias[n] : 0.f);
                if (mode == 0) {
                    C[(long)m * ldc + n] = v;
                } else {
                    int hh = n >> 6;
                    C[(long)hh * headM * 64 + (long)m * 64 + (n & 63)] = v;
                }
            }
        }
    }
}

// ---------------- fused attention ----------------
// grid: (S/TI, H, B), block 256, dynamic smem.
// logits[i,j] = (q_i . k_j + QPK[i, j-i+383] + KPQ[j, j-i+383]) * SCALE
// then mask, softmax over j, then P @ V -> vals[b,s, h*64+d]
#define TI 32
#define LDK 68
#define LDP 33
#define LDL 385
#define ATT_SMEM_FLOATS (TI*DD + 64*LDK + 64*LDP + TI*LDL)   // 20832
#define ATT_SMEM_BYTES  (ATT_SMEM_FLOATS*4)                  // 83328

__global__ __launch_bounds__(256)
void attn_kernel(const float* __restrict__ Q, const float* __restrict__ K,
                 const float* __restrict__ V,
                 const float* __restrict__ QPK, const float* __restrict__ KPQ,
                 const int* __restrict__ mask, float* __restrict__ vals)
{
    extern __shared__ float sm[];
    float* sQ   = sm;                       // TI*64
    float* sKV  = sQ + TI * DD;             // 64*LDK (K tile, later V tile)
    float* sP2C = sKV + 64 * LDK;           // 64*LDP
    float* sL   = sP2C + 64 * LDP;          // TI*LDL

    int i0  = blockIdx.x * TI;
    int h   = blockIdx.y;
    int b   = blockIdx.z;
    int tid = threadIdx.x;

    long baseRow = (long)h * BSROWS + (long)b * SS;

    // load Q tile
    for (int idx = tid; idx < TI * DD; idx += 256) {
        int r = idx >> 6, d = idx & 63;
        sQ[idx] = Q[(baseRow + i0 + r) * DD + d];
    }

    int tx = tid & 15, ty = tid >> 4;
    int r0 = ty * 2, c0 = tx * 4;

    // ------- phase A: logits -------
    for (int jt = 0; jt < SS / 64; jt++) {
        int j0 = jt * 64;
        __syncthreads();
        for (int idx = tid; idx < 64 * 64; idx += 256) {
            int r = idx >> 6, d = idx & 63;
            sKV[r * LDK + d] = K[(baseRow + j0 + r) * DD + d];
        }
        // stage p2c band: sP2C[jj][r] = KPQ[row j0+jj][ (j0+jj) - (i0+r) + 383 ]
        for (int idx = tid; idx < 64 * TI; idx += 256) {
            int jj = idx >> 5, r = idx & 31;
            int j = j0 + jj;
            sP2C[jj * LDP + r] = KPQ[(baseRow + j) * LDT + (j - (i0 + r) + 383)];
        }
        __syncthreads();

        float acc[2][4];
#pragma unroll
        for (int r = 0; r < 2; r++)
#pragma unroll
            for (int c = 0; c < 4; c++) acc[r][c] = 0.f;

#pragma unroll 16
        for (int d = 0; d < 64; d++) {
            float a0 = sQ[(r0 + 0) * DD + d];
            float a1 = sQ[(r0 + 1) * DD + d];
            float b0 = sKV[(c0 + 0) * LDK + d];
            float b1 = sKV[(c0 + 1) * LDK + d];
            float b2 = sKV[(c0 + 2) * LDK + d];
            float b3 = sKV[(c0 + 3) * LDK + d];
            acc[0][0] += a0 * b0; acc[0][1] += a0 * b1;
            acc[0][2] += a0 * b2; acc[0][3] += a0 * b3;
            acc[1][0] += a1 * b0; acc[1][1] += a1 * b1;
            acc[1][2] += a1 * b2; acc[1][3] += a1 * b3;
        }

#pragma unroll
        for (int r = 0; r < 2; r++) {
            int i = i0 + r0 + r;
            const float* qpkRow = QPK + (baseRow + i) * LDT + 383 - i;
#pragma unroll
            for (int c = 0; c < 4; c++) {
                int j = j0 + c0 + c;
                float l = acc[r][c] + qpkRow[j] + sP2C[(c0 + c) * LDP + (r0 + r)];
                l *= SCALE_F;
                if (__ldg(&mask[b * SS + j]) == 0) l = -9.0e15f;
                sL[(r0 + r) * LDL + j] = l;
            }
        }
    }
    __syncthreads();

    // ------- phase B: row softmax (warp per 4 rows) -------
    int warp = tid >> 5, lane = tid & 31;
    for (int rr = 0; rr < 4; rr++) {
        int r = warp * 4 + rr;
        float mx = -INFINITY;
        for (int j = lane; j < SS; j += 32) mx = fmaxf(mx, sL[r * LDL + j]);
#pragma unroll
        for (int o = 16; o > 0; o >>= 1) mx = fmaxf(mx, __shfl_xor_sync(0xffffffffu, mx, o));
        float sum = 0.f;
        for (int j = lane; j < SS; j += 32) {
            float e = __expf(sL[r * LDL + j] - mx);
            sL[r * LDL + j] = e;
            sum += e;
        }
#pragma unroll
        for (int o = 16; o > 0; o >>= 1) sum += __shfl_xor_sync(0xffffffffu, sum, o);
        float inv = 1.f / sum;
        for (int j = lane; j < SS; j += 32) sL[r * LDL + j] *= inv;
    }

    // ------- phase C: P @ V -------
    float out[2][4];
#pragma unroll
    for (int r = 0; r < 2; r++)
#pragma unroll
        for (int c = 0; c < 4; c++) out[r][c] = 0.f;

    for (int jt = 0; jt < SS / 64; jt++) {
        int j0 = jt * 64;
        __syncthreads();
        for (int idx = tid; idx < 64 * 64; idx += 256) {
            int r = idx >> 6, d = idx & 63;
            sKV[r * LDK + d] = V[(baseRow + j0 + r) * DD + d];
        }
        __syncthreads();
#pragma unroll 8
        for (int jj = 0; jj < 64; jj++) {
            float p0 = sL[(r0 + 0) * LDL + j0 + jj];
            float p1 = sL[(r0 + 1) * LDL + j0 + jj];
            float v0 = sKV[jj * LDK + c0 + 0];
            float v1 = sKV[jj * LDK + c0 + 1];
            float v2 = sKV[jj * LDK + c0 + 2];
            float v3 = sKV[jj * LDK + c0 + 3];
            out[0][0] += p0 * v0; out[0][1] += p0 * v1;
            out[0][2] += p0 * v2; out[0][3] += p0 * v3;
            out[1][0] += p1 * v0; out[1][1] += p1 * v1;
            out[1][2] += p1 * v2; out[1][3] += p1 * v3;
        }
    }

#pragma unroll
    for (int r = 0; r < 2; r++) {
        int i = i0 + r0 + r;
#pragma unroll
        for (int c = 0; c < 4; c++) {
            vals[(long)(b * SS + i) * EE + h * DD + (c0 + c)] = out[r][c];
        }
    }
}

// ---------------- launch ----------------
extern "C" void kernel_launch(void* const* d_in, const int* in_sizes, int n_in,
                              void* d_out, int out_size)
{
    const float* x    = (const float*)d_in[0];
    const int*   mask = (const int*)  d_in[1];
    const float* Wq   = (const float*)d_in[2];
    const float* bq   = (const float*)d_in[3];
    const float* Wk   = (const float*)d_in[4];
    const float* bk   = (const float*)d_in[5];
    const float* Wv   = (const float*)d_in[6];
    const float* bv   = (const float*)d_in[7];
    const float* relt = (const float*)d_in[8];
    const float* Wpk  = (const float*)d_in[9];
    const float* bpk  = (const float*)d_in[10];
    const float* Wpq  = (const float*)d_in[11];
    const float* bpq  = (const float*)d_in[12];
    const float* Wo   = (const float*)d_in[13];
    const float* bo   = (const float*)d_in[14];
    float* out = (float*)d_out;

    float *Q, *K, *V, *PK, *PQ, *QPK, *KPQ, *VALS;
    cudaGetSymbolAddress((void**)&Q,   g_Q);
    cudaGetSymbolAddress((void**)&K,   g_K);
    cudaGetSymbolAddress((void**)&V,   g_V);
    cudaGetSymbolAddress((void**)&PK,  g_PK);
    cudaGetSymbolAddress((void**)&PQ,  g_PQ);
    cudaGetSymbolAddress((void**)&QPK, g_QPK);
    cudaGetSymbolAddress((void**)&KPQ, g_KPQ);
    cudaGetSymbolAddress((void**)&VALS, g_vals);

    dim3 blk(256);

    // QKV projections -> head-split [H][B*S][64]
    gemm_nt<<<dim3(8, 48, 1), blk>>>(x, IN_DIM, 0, Wq, IN_DIM, 0, bq, Q, 0,
                                     BSROWS, EE, IN_DIM, 1, 0, BSROWS);
    gemm_nt<<<dim3(8, 48, 1), blk>>>(x, IN_DIM, 0, Wk, IN_DIM, 0, bk, K, 0,
                                     BSROWS, EE, IN_DIM, 1, 0, BSROWS);
    gemm_nt<<<dim3(8, 48, 1), blk>>>(x, IN_DIM, 0, Wv, IN_DIM, 0, bv, V, 0,
                                     BSROWS, EE, IN_DIM, 1, 0, BSROWS);

    // positional tables (only 767 distinct rel rows!) -> [H][767][64]
    gemm_nt<<<dim3(8, 12, 1), blk>>>(relt + (long)REL_OFF * IN_DIM, IN_DIM, 0,
                                     Wpk, IN_DIM, 0, bpk, PK, 0,
                                     ND, EE, IN_DIM, 1, 0, ND);
    gemm_nt<<<dim3(8, 12, 1), blk>>>(relt + (long)REL_OFF * IN_DIM, IN_DIM, 0,
                                     Wpq, IN_DIM, 0, bpq, PQ, 0,
                                     ND, EE, IN_DIM, 1, 0, ND);

    // per-head QPK = Q_h @ PK_h^T, KPQ = K_h @ PQ_h^T   (batched over heads)
    gemm_nt<<<dim3(12, 48, HH), blk>>>(Q, DD, (long)BSROWS * DD,
                                       PK, DD, (long)ND * DD, nullptr,
                                       QPK, (long)BSROWS * LDT,
                                       BSROWS, ND, DD, 0, LDT, 0);
    gemm_nt<<<dim3(12, 48, HH), blk>>>(K, DD, (long)BSROWS * DD,
                                       PQ, DD, (long)ND * DD, nullptr,
                                       KPQ, (long)BSROWS * LDT,
                                       BSROWS, ND, DD, 0, LDT, 0);

    // fused attention
    cudaFuncSetAttribute(attn_kernel, cudaFuncAttributeMaxDynamicSharedMemorySize,
                         ATT_SMEM_BYTES);
    attn_kernel<<<dim3(SS / TI, HH, BB), blk, ATT_SMEM_BYTES>>>(
        Q, K, V, QPK, KPQ, mask, VALS);

    // output projection
    gemm_nt<<<dim3(8, 48, 1), blk>>>(VALS, EE, 0, Wo, EE, 0, bo, out, 0,
                                     BSROWS, IN_DIM, EE, 0, IN_DIM, 0);
}

// round 5
// speedup vs baseline: 1.4777x; 1.4777x over previous
#include <cuda_runtime.h>
#include <math.h>

// ---------------- problem constants ----------------
#define BB 8
#define SS 384
#define IN_DIM 512
#define EE 512
#define HH 8
#define DD 64
#define BSROWS (BB*SS)        // 3072
#define ND 767                // distinct rel offsets used: j-i+383 in [0,766]
#define LDT 768               // padded leading dim for QPK/KPQ
#define REL_OFF 128           // rel_table row offset: table row = t + 128
#define SCALE_F 0.07216878364870323f   // 1/sqrt(64*3)

// ---------------- scratch (__device__ globals; no runtime allocation) ------
__device__ float g_Q[(size_t)HH*BSROWS*DD];
__device__ float g_K[(size_t)HH*BSROWS*DD];
__device__ float g_V[(size_t)HH*BSROWS*DD];
__device__ float g_PK[(size_t)HH*ND*DD];
__device__ float g_PQ[(size_t)HH*ND*DD];
__device__ float g_QPK[(size_t)HH*BSROWS*LDT];
__device__ float g_KPQ[(size_t)HH*BSROWS*LDT];
__device__ float g_vals[(size_t)BSROWS*EE];

// ---------------- generic NT SGEMM: C = A(MxK) * B(NxK)^T + bias ----------
// mode 0: C[m*ldc + n]
// mode 1: head-split: h=n>>6, C[h*headM*64 + m*64 + (n&63)]
// band: 0 none; 1 QPK band skip; 2 KPQ band skip (rows are (b,s), s0 = m0%SS)
__global__ __launch_bounds__(256)
void gemm_nt(const float* __restrict__ A, int lda, long sA,
             const float* __restrict__ Bm, int ldb, long sB,
             const float* __restrict__ bias,
             float* __restrict__ C, long sC,
             int M, int N, int K,
             int mode, int ldc, int headM, int band)
{
    int m0 = blockIdx.y * 64;
    int n0 = blockIdx.x * 64;

    if (band) {
        int s0 = m0 % SS;
        if (band == 1) {            // QPK: t needed in [320-s0, 766-s0]
            if (n0 + 63 < 320 - s0 || n0 > 766 - s0) return;
        } else {                     // KPQ: t needed in [s0, s0+446]
            if (n0 + 63 < s0 || n0 > s0 + 446) return;
        }
    }

    int bz = blockIdx.z;
    A  += (long)bz * sA;
    Bm += (long)bz * sB;
    C  += (long)bz * sC;

    __shared__ float As[16][65];
    __shared__ float Bs[16][65];

    int tid = threadIdx.x;
    int tx = tid & 15, ty = tid >> 4;

    float acc[4][4];
#pragma unroll
    for (int i = 0; i < 4; i++)
#pragma unroll
        for (int j = 0; j < 4; j++) acc[i][j] = 0.f;

    int lrow = tid >> 2;
    int lcol = (tid & 3) * 4;

    for (int k0 = 0; k0 < K; k0 += 16) {
        {
            int m = m0 + lrow;
            float4 v = make_float4(0.f, 0.f, 0.f, 0.f);
            if (m < M) v = *(const float4*)(A + (long)m * lda + k0 + lcol);
            As[lcol + 0][lrow] = v.x; As[lcol + 1][lrow] = v.y;
            As[lcol + 2][lrow] = v.z; As[lcol + 3][lrow] = v.w;
        }
        {
            int n = n0 + lrow;
            float4 v = make_float4(0.f, 0.f, 0.f, 0.f);
            if (n < N) v = *(const float4*)(Bm + (long)n * ldb + k0 + lcol);
            Bs[lcol + 0][lrow] = v.x; Bs[lcol + 1][lrow] = v.y;
            Bs[lcol + 2][lrow] = v.z; Bs[lcol + 3][lrow] = v.w;
        }
        __syncthreads();
#pragma unroll
        for (int kk = 0; kk < 16; kk++) {
            float a[4], b[4];
#pragma unroll
            for (int i = 0; i < 4; i++) a[i] = As[kk][ty * 4 + i];
#pragma unroll
            for (int j = 0; j < 4; j++) b[j] = Bs[kk][tx * 4 + j];
#pragma unroll
            for (int i = 0; i < 4; i++)
#pragma unroll
                for (int j = 0; j < 4; j++) acc[i][j] += a[i] * b[j];
        }
        __syncthreads();
    }

#pragma unroll
    for (int i = 0; i < 4; i++) {
#pragma unroll
        for (int j = 0; j < 4; j++) {
            int m = m0 + ty * 4 + i;
            int n = n0 + tx * 4 + j;
            if (m < M && n < N) {
                float v = acc[i][j] + (bias ? bias[n] : 0.f);
                if (mode == 0) {
                    C[(long)m * ldc + n] = v;
                } else {
                    int hh = n >> 6;
                    C[(long)hh * headM * 64 + (long)m * 64 + (n & 63)] = v;
                }
            }
        }
    }
}

// ------------- merged projection kernel: Q,K,V,PK,PQ in one launch --------
// 1344 blocks: [0,1152) QKV (3 ops x 48 m-tiles x 8 n-tiles), [1152,1344) PK/PQ
__global__ __launch_bounds__(256)
void proj_all(const float* __restrict__ x, const float* __restrict__ relt,
              const float* __restrict__ Wq, const float* __restrict__ bq,
              const float* __restrict__ Wk, const float* __restrict__ bk,
              const float* __restrict__ Wv, const float* __restrict__ bv,
              const float* __restrict__ Wpk, const float* __restrict__ bpk,
              const float* __restrict__ Wpq, const float* __restrict__ bpq,
              float* __restrict__ Qo, float* __restrict__ Ko, float* __restrict__ Vo,
              float* __restrict__ PKo, float* __restrict__ PQo)
{
    int id = blockIdx.x;
    const float *A, *Bw, *bias; float* C;
    int M, headM, m0, n0;
    if (id < 1152) {
        int op = id / 384, rem = id % 384;
        m0 = (rem >> 3) * 64; n0 = (rem & 7) * 64;
        A = x; M = BSROWS; headM = BSROWS;
        if (op == 0)      { Bw = Wq; bias = bq; C = Qo; }
        else if (op == 1) { Bw = Wk; bias = bk; C = Ko; }
        else              { Bw = Wv; bias = bv; C = Vo; }
    } else {
        int id2 = id - 1152;
        int op = id2 / 96, rem = id2 % 96;
        m0 = (rem >> 3) * 64; n0 = (rem & 7) * 64;
        A = relt + (long)REL_OFF * IN_DIM; M = ND; headM = ND;
        if (op == 0) { Bw = Wpk; bias = bpk; C = PKo; }
        else         { Bw = Wpq; bias = bpq; C = PQo; }
    }

    __shared__ float As[16][65];
    __shared__ float Bs[16][65];

    int tid = threadIdx.x;
    int tx = tid & 15, ty = tid >> 4;

    float acc[4][4];
#pragma unroll
    for (int i = 0; i < 4; i++)
#pragma unroll
        for (int j = 0; j < 4; j++) acc[i][j] = 0.f;

    int lrow = tid >> 2;
    int lcol = (tid & 3) * 4;

    for (int k0 = 0; k0 < IN_DIM; k0 += 16) {
        {
            int m = m0 + lrow;
            float4 v = make_float4(0.f, 0.f, 0.f, 0.f);
            if (m < M) v = *(const float4*)(A + (long)m * IN_DIM + k0 + lcol);
            As[lcol + 0][lrow] = v.x; As[lcol + 1][lrow] = v.y;
            As[lcol + 2][lrow] = v.z; As[lcol + 3][lrow] = v.w;
        }
        {
            int n = n0 + lrow;
            float4 v = *(const float4*)(Bw + (long)n * IN_DIM + k0 + lcol);
            Bs[lcol + 0][lrow] = v.x; Bs[lcol + 1][lrow] = v.y;
            Bs[lcol + 2][lrow] = v.z; Bs[lcol + 3][lrow] = v.w;
        }
        __syncthreads();
#pragma unroll
        for (int kk = 0; kk < 16; kk++) {
            float a[4], b[4];
#pragma unroll
            for (int i = 0; i < 4; i++) a[i] = As[kk][ty * 4 + i];
#pragma unroll
            for (int j = 0; j < 4; j++) b[j] = Bs[kk][tx * 4 + j];
#pragma unroll
            for (int i = 0; i < 4; i++)
#pragma unroll
                for (int j = 0; j < 4; j++) acc[i][j] += a[i] * b[j];
        }
        __syncthreads();
    }

#pragma unroll
    for (int i = 0; i < 4; i++) {
#pragma unroll
        for (int j = 0; j < 4; j++) {
            int m = m0 + ty * 4 + i;
            int n = n0 + tx * 4 + j;
            if (m < M) {
                float v = acc[i][j] + bias[n];
                int hh = n >> 6;
                C[(long)hh * headM * 64 + (long)m * 64 + (n & 63)] = v;
            }
        }
    }
}

// ---------------- fused attention (swizzled float4 tiles) ----------------
// logits[i,j] = (q_i . k_j + QPK[i, j-i+383] + KPQ[j, j-i+383]) * SCALE
#define TI 32
#define LDP 33
#define LDL 385
// XOR swizzle: element (row, d) -> float4 slot row*16 + (d4 ^ ((row>>2)&15))
#define SW4(row, d4) (((row) << 4) + ((d4) ^ (((row) >> 2) & 15)))
#define ATT_SMEM_BYTES ((512 + 1024) * 16 + (64 * LDP + TI * LDL) * 4)   // 82304

__global__ __launch_bounds__(256)
void attn_kernel(const float* __restrict__ Q, const float* __restrict__ K,
                 const float* __restrict__ V,
                 const float* __restrict__ QPK, const float* __restrict__ KPQ,
                 const int* __restrict__ mask, float* __restrict__ vals)
{
    extern __shared__ float4 sm4[];
    float4* sQ4  = sm4;            // 32 rows x 16 slots
    float4* sKV4 = sm4 + 512;      // 64 rows x 16 slots (K tile, later V tile)
    float*  sP2C = (float*)(sm4 + 1536);   // 64*LDP
    float*  sL   = sP2C + 64 * LDP;        // TI*LDL

    int i0  = blockIdx.x * TI;
    int h   = blockIdx.y;
    int b   = blockIdx.z;
    int tid = threadIdx.x;

    long baseRow = (long)h * BSROWS + (long)b * SS;

    // load Q tile (32 rows x 64 d) swizzled
    {
        const float4* Qg = (const float4*)(Q + (baseRow + i0) * DD);
        for (int idx = tid; idx < TI * 16; idx += 256) {
            int r = idx >> 4, d4 = idx & 15;
            sQ4[SW4(r, d4)] = Qg[idx];
        }
    }

    int tx = tid & 15, ty = tid >> 4;
    int r0 = ty * 2, c0 = tx * 4;

    // ------- phase A: logits -------
    for (int jt = 0; jt < SS / 64; jt++) {
        int j0 = jt * 64;
        __syncthreads();
        {
            const float4* Kg = (const float4*)(K + (baseRow + j0) * DD);
            for (int idx = tid; idx < 64 * 16; idx += 256) {
                int r = idx >> 4, d4 = idx & 15;
                sKV4[SW4(r, d4)] = Kg[idx];
            }
        }
        // stage p2c band: sP2C[jj][r] = KPQ[row j0+jj][ (j0+jj) - (i0+r) + 383 ]
        for (int idx = tid; idx < 64 * TI; idx += 256) {
            int jj = idx >> 5, r = idx & 31;
            int j = j0 + jj;
            sP2C[jj * LDP + r] = KPQ[(baseRow + j) * LDT + (j - (i0 + r) + 383)];
        }
        __syncthreads();

        float acc[2][4];
#pragma unroll
        for (int r = 0; r < 2; r++)
#pragma unroll
            for (int c = 0; c < 4; c++) acc[r][c] = 0.f;

#pragma unroll
        for (int d4 = 0; d4 < 16; d4++) {
            float4 a0 = sQ4[SW4(r0 + 0, d4)];
            float4 a1 = sQ4[SW4(r0 + 1, d4)];
            float4 b0 = sKV4[SW4(c0 + 0, d4)];
            float4 b1 = sKV4[SW4(c0 + 1, d4)];
            float4 b2 = sKV4[SW4(c0 + 2, d4)];
            float4 b3 = sKV4[SW4(c0 + 3, d4)];
            acc[0][0] += a0.x*b0.x + a0.y*b0.y + a0.z*b0.z + a0.w*b0.w;
            acc[0][1] += a0.x*b1.x + a0.y*b1.y + a0.z*b1.z + a0.w*b1.w;
            acc[0][2] += a0.x*b2.x + a0.y*b2.y + a0.z*b2.z + a0.w*b2.w;
            acc[0][3] += a0.x*b3.x + a0.y*b3.y + a0.z*b3.z + a0.w*b3.w;
            acc[1][0] += a1.x*b0.x + a1.y*b0.y + a1.z*b0.z + a1.w*b0.w;
            acc[1][1] += a1.x*b1.x + a1.y*b1.y + a1.z*b1.z + a1.w*b1.w;
            acc[1][2] += a1.x*b2.x + a1.y*b2.y + a1.z*b2.z + a1.w*b2.w;
            acc[1][3] += a1.x*b3.x + a1.y*b3.y + a1.z*b3.z + a1.w*b3.w;
        }

#pragma unroll
        for (int r = 0; r < 2; r++) {
            int i = i0 + r0 + r;
            const float* qpkRow = QPK + (baseRow + i) * LDT + 383 - i;
#pragma unroll
            for (int c = 0; c < 4; c++) {
                int j = j0 + c0 + c;
                float l = acc[r][c] + qpkRow[j] + sP2C[(c0 + c) * LDP + (r0 + r)];
                l *= SCALE_F;
                if (__ldg(&mask[b * SS + j]) == 0) l = -9.0e15f;
                sL[(r0 + r) * LDL + j] = l;
            }
        }
    }
    __syncthreads();

    // ------- phase B: row softmax -------
    int warp = tid >> 5, lane = tid & 31;
    for (int rr = 0; rr < 4; rr++) {
        int r = warp * 4 + rr;
        float mx = -INFINITY;
        for (int j = lane; j < SS; j += 32) mx = fmaxf(mx, sL[r * LDL + j]);
#pragma unroll
        for (int o = 16; o > 0; o >>= 1) mx = fmaxf(mx, __shfl_xor_sync(0xffffffffu, mx, o));
        float sum = 0.f;
        for (int j = lane; j < SS; j += 32) {
            float e = __expf(sL[r * LDL + j] - mx);
            sL[r * LDL + j] = e;
            sum += e;
        }
#pragma unroll
        for (int o = 16; o > 0; o >>= 1) sum += __shfl_xor_sync(0xffffffffu, sum, o);
        float inv = 1.f / sum;
        for (int j = lane; j < SS; j += 32) sL[r * LDL + j] *= inv;
    }

    // ------- phase C: P @ V -------
    float out[2][4];
#pragma unroll
    for (int r = 0; r < 2; r++)
#pragma unroll
        for (int c = 0; c < 4; c++) out[r][c] = 0.f;

    for (int jt = 0; jt < SS / 64; jt++) {
        int j0 = jt * 64;
        __syncthreads();
        {
            const float4* Vg = (const float4*)(V + (baseRow + j0) * DD);
            for (int idx = tid; idx < 64 * 16; idx += 256) {
                int r = idx >> 4, d4 = idx & 15;
                sKV4[SW4(r, d4)] = Vg[idx];
            }
        }
        __syncthreads();
#pragma unroll 4
        for (int jj = 0; jj < 64; jj++) {
            float p0 = sL[(r0 + 0) * LDL + j0 + jj];
            float p1 = sL[(r0 + 1) * LDL + j0 + jj];
            float4 vv = sKV4[SW4(jj, tx)];
            out[0][0] += p0 * vv.x; out[0][1] += p0 * vv.y;
            out[0][2] += p0 * vv.z; out[0][3] += p0 * vv.w;
            out[1][0] += p1 * vv.x; out[1][1] += p1 * vv.y;
            out[1][2] += p1 * vv.z; out[1][3] += p1 * vv.w;
        }
    }

#pragma unroll
    for (int r = 0; r < 2; r++) {
        int i = i0 + r0 + r;
#pragma unroll
        for (int c = 0; c < 4; c++) {
            vals[(long)(b * SS + i) * EE + h * DD + (c0 + c)] = out[r][c];
        }
    }
}

// ---------------- launch ----------------
extern "C" void kernel_launch(void* const* d_in, const int* in_sizes, int n_in,
                              void* d_out, int out_size)
{
    const float* x    = (const float*)d_in[0];
    const int*   mask = (const int*)  d_in[1];
    const float* Wq   = (const float*)d_in[2];
    const float* bq   = (const float*)d_in[3];
    const float* Wk   = (const float*)d_in[4];
    const float* bk   = (const float*)d_in[5];
    const float* Wv   = (const float*)d_in[6];
    const float* bv   = (const float*)d_in[7];
    const float* relt = (const float*)d_in[8];
    const float* Wpk  = (const float*)d_in[9];
    const float* bpk  = (const float*)d_in[10];
    const float* Wpq  = (const float*)d_in[11];
    const float* bpq  = (const float*)d_in[12];
    const float* Wo   = (const float*)d_in[13];
    const float* bo   = (const float*)d_in[14];
    float* out = (float*)d_out;

    float *Q, *K, *V, *PK, *PQ, *QPK, *KPQ, *VALS;
    cudaGetSymbolAddress((void**)&Q,   g_Q);
    cudaGetSymbolAddress((void**)&K,   g_K);
    cudaGetSymbolAddress((void**)&V,   g_V);
    cudaGetSymbolAddress((void**)&PK,  g_PK);
    cudaGetSymbolAddress((void**)&PQ,  g_PQ);
    cudaGetSymbolAddress((void**)&QPK, g_QPK);
    cudaGetSymbolAddress((void**)&KPQ, g_KPQ);
    cudaGetSymbolAddress((void**)&VALS, g_vals);

    dim3 blk(256);

    // merged QKV + positional table projections (one big launch)
    proj_all<<<dim3(1344), blk>>>(x, relt, Wq, bq, Wk, bk, Wv, bv,
                                  Wpk, bpk, Wpq, bpq, Q, K, V, PK, PQ);

    // per-head QPK = Q_h @ PK_h^T, KPQ = K_h @ PQ_h^T  (band-skipped)
    gemm_nt<<<dim3(12, 48, HH), blk>>>(Q, DD, (long)BSROWS * DD,
                                       PK, DD, (long)ND * DD, nullptr,
                                       QPK, (long)BSROWS * LDT,
                                       BSROWS, ND, DD, 0, LDT, 0, 1);
    gemm_nt<<<dim3(12, 48, HH), blk>>>(K, DD, (long)BSROWS * DD,
                                       PQ, DD, (long)ND * DD, nullptr,
                                       KPQ, (long)BSROWS * LDT,
                                       BSROWS, ND, DD, 0, LDT, 0, 2);

    // fused attention
    cudaFuncSetAttribute(attn_kernel, cudaFuncAttributeMaxDynamicSharedMemorySize,
                         ATT_SMEM_BYTES);
    attn_kernel<<<dim3(SS / TI, HH, BB), blk, ATT_SMEM_BYTES>>>(
        Q, K, V, QPK, KPQ, mask, VALS);

    // output projection
    gemm_nt<<<dim3(8, 48, 1), blk>>>(VALS, EE, 0, Wo, EE, 0, bo, out, 0,
                                     BSROWS, IN_DIM, EE, 0, IN_DIM, 0, 0);
}

// round 6
// speedup vs baseline: 1.5901x; 1.0761x over previous
#include <cuda_runtime.h>
#include <math.h>

// ---------------- problem constants ----------------
#define BB 8
#define SS 384
#define IN_DIM 512
#define EE 512
#define HH 8
#define DD 64
#define BSROWS (BB*SS)        // 3072
#define ND 767                // distinct rel offsets used: j-i+383 in [0,766]
#define LDT 768               // padded leading dim for QPK/KPQ
#define REL_OFF 128           // rel_table row offset: table row = t + 128
#define SCALE_F 0.07216878364870323f   // 1/sqrt(64*3)

// ---------------- scratch (__device__ globals) ------
__device__ float g_Q[(size_t)HH*BSROWS*DD];
__device__ float g_K[(size_t)HH*BSROWS*DD];
__device__ float g_V[(size_t)HH*BSROWS*DD];
__device__ float g_PK[(size_t)HH*ND*DD];
__device__ float g_PQ[(size_t)HH*ND*DD];
__device__ float g_QPK[(size_t)HH*BSROWS*LDT];
__device__ float g_KPQ[(size_t)HH*BSROWS*LDT];
__device__ float g_vals[(size_t)BSROWS*EE];

// ---------------- generic NT SGEMM (used for output projection) ----------
__global__ __launch_bounds__(256)
void gemm_nt(const float* __restrict__ A, int lda,
             const float* __restrict__ Bm, int ldb,
             const float* __restrict__ bias,
             float* __restrict__ C, int ldc,
             int M, int N, int K)
{
    int m0 = blockIdx.y * 64;
    int n0 = blockIdx.x * 64;

    __shared__ float As[16][65];
    __shared__ float Bs[16][65];

    int tid = threadIdx.x;
    int tx = tid & 15, ty = tid >> 4;

    float acc[4][4];
#pragma unroll
    for (int i = 0; i < 4; i++)
#pragma unroll
        for (int j = 0; j < 4; j++) acc[i][j] = 0.f;

    int lrow = tid >> 2;
    int lcol = (tid & 3) * 4;

    for (int k0 = 0; k0 < K; k0 += 16) {
        {
            int m = m0 + lrow;
            float4 v = make_float4(0.f, 0.f, 0.f, 0.f);
            if (m < M) v = *(const float4*)(A + (long)m * lda + k0 + lcol);
            As[lcol + 0][lrow] = v.x; As[lcol + 1][lrow] = v.y;
            As[lcol + 2][lrow] = v.z; As[lcol + 3][lrow] = v.w;
        }
        {
            int n = n0 + lrow;
            float4 v = make_float4(0.f, 0.f, 0.f, 0.f);
            if (n < N) v = *(const float4*)(Bm + (long)n * ldb + k0 + lcol);
            Bs[lcol + 0][lrow] = v.x; Bs[lcol + 1][lrow] = v.y;
            Bs[lcol + 2][lrow] = v.z; Bs[lcol + 3][lrow] = v.w;
        }
        __syncthreads();
#pragma unroll
        for (int kk = 0; kk < 16; kk++) {
            float a[4], b[4];
#pragma unroll
            for (int i = 0; i < 4; i++) a[i] = As[kk][ty * 4 + i];
#pragma unroll
            for (int j = 0; j < 4; j++) b[j] = Bs[kk][tx * 4 + j];
#pragma unroll
            for (int i = 0; i < 4; i++)
#pragma unroll
                for (int j = 0; j < 4; j++) acc[i][j] += a[i] * b[j];
        }
        __syncthreads();
    }

#pragma unroll
    for (int i = 0; i < 4; i++) {
#pragma unroll
        for (int j = 0; j < 4; j++) {
            int m = m0 + ty * 4 + i;
            int n = n0 + tx * 4 + j;
            if (m < M && n < N)
                C[(long)m * ldc + n] = acc[i][j] + bias[n];
        }
    }
}

// ------------- merged positional GEMM: QPK (z<8) and KPQ (z>=8) ----------
// C = A(BSROWS x 64) * B(767 x 64)^T  with band skip.
__global__ __launch_bounds__(256)
void pos_gemm(const float* __restrict__ Qm, const float* __restrict__ Km,
              const float* __restrict__ PKm, const float* __restrict__ PQm,
              float* __restrict__ QPKo, float* __restrict__ KPQo)
{
    int m0 = blockIdx.y * 64;
    int n0 = blockIdx.x * 64;
    int z  = blockIdx.z;

    const float *A, *Bm; float* C; int band;
    if (z < 8) {
        A = Qm + (long)z * BSROWS * DD; Bm = PKm + (long)z * ND * DD;
        C = QPKo + (long)z * BSROWS * LDT; band = 1;
    } else {
        int h = z - 8;
        A = Km + (long)h * BSROWS * DD; Bm = PQm + (long)h * ND * DD;
        C = KPQo + (long)h * BSROWS * LDT; band = 2;
    }

    int s0 = m0 % SS;
    if (band == 1) {            // QPK: t needed in [320-s0, 766-s0]
        if (n0 + 63 < 320 - s0 || n0 > 766 - s0) return;
    } else {                    // KPQ: t needed in [s0, s0+446]
        if (n0 + 63 < s0 || n0 > s0 + 446) return;
    }

    __shared__ float As[16][65];
    __shared__ float Bs[16][65];

    int tid = threadIdx.x;
    int tx = tid & 15, ty = tid >> 4;

    float acc[4][4];
#pragma unroll
    for (int i = 0; i < 4; i++)
#pragma unroll
        for (int j = 0; j < 4; j++) acc[i][j] = 0.f;

    int lrow = tid >> 2;
    int lcol = (tid & 3) * 4;

    for (int k0 = 0; k0 < DD; k0 += 16) {
        {
            int m = m0 + lrow;
            float4 v = *(const float4*)(A + (long)m * DD + k0 + lcol);
            As[lcol + 0][lrow] = v.x; As[lcol + 1][lrow] = v.y;
            As[lcol + 2][lrow] = v.z; As[lcol + 3][lrow] = v.w;
        }
        {
            int n = n0 + lrow;
            float4 v = make_float4(0.f, 0.f, 0.f, 0.f);
            if (n < ND) v = *(const float4*)(Bm + (long)n * DD + k0 + lcol);
            Bs[lcol + 0][lrow] = v.x; Bs[lcol + 1][lrow] = v.y;
            Bs[lcol + 2][lrow] = v.z; Bs[lcol + 3][lrow] = v.w;
        }
        __syncthreads();
#pragma unroll
        for (int kk = 0; kk < 16; kk++) {
            float a[4], b[4];
#pragma unroll
            for (int i = 0; i < 4; i++) a[i] = As[kk][ty * 4 + i];
#pragma unroll
            for (int j = 0; j < 4; j++) b[j] = Bs[kk][tx * 4 + j];
#pragma unroll
            for (int i = 0; i < 4; i++)
#pragma unroll
                for (int j = 0; j < 4; j++) acc[i][j] += a[i] * b[j];
        }
        __syncthreads();
    }

#pragma unroll
    for (int i = 0; i < 4; i++) {
#pragma unroll
        for (int j = 0; j < 4; j++) {
            int m = m0 + ty * 4 + i;
            int n = n0 + tx * 4 + j;
            if (n < ND)
                C[(long)m * LDT + n] = acc[i][j];
        }
    }
}

// ------------- merged projection kernel: Q,K,V,PK,PQ in one launch --------
__global__ __launch_bounds__(256)
void proj_all(const float* __restrict__ x, const float* __restrict__ relt,
              const float* __restrict__ Wq, const float* __restrict__ bq,
              const float* __restrict__ Wk, const float* __restrict__ bk,
              const float* __restrict__ Wv, const float* __restrict__ bv,
              const float* __restrict__ Wpk, const float* __restrict__ bpk,
              const float* __restrict__ Wpq, const float* __restrict__ bpq,
              float* __restrict__ Qo, float* __restrict__ Ko, float* __restrict__ Vo,
              float* __restrict__ PKo, float* __restrict__ PQo)
{
    int id = blockIdx.x;
    const float *A, *Bw, *bias; float* C;
    int M, headM, m0, n0;
    if (id < 1152) {
        int op = id / 384, rem = id % 384;
        m0 = (rem >> 3) * 64; n0 = (rem & 7) * 64;
        A = x; M = BSROWS; headM = BSROWS;
        if (op == 0)      { Bw = Wq; bias = bq; C = Qo; }
        else if (op == 1) { Bw = Wk; bias = bk; C = Ko; }
        else              { Bw = Wv; bias = bv; C = Vo; }
    } else {
        int id2 = id - 1152;
        int op = id2 / 96, rem = id2 % 96;
        m0 = (rem >> 3) * 64; n0 = (rem & 7) * 64;
        A = relt + (long)REL_OFF * IN_DIM; M = ND; headM = ND;
        if (op == 0) { Bw = Wpk; bias = bpk; C = PKo; }
        else         { Bw = Wpq; bias = bpq; C = PQo; }
    }

    __shared__ float As[16][65];
    __shared__ float Bs[16][65];

    int tid = threadIdx.x;
    int tx = tid & 15, ty = tid >> 4;

    float acc[4][4];
#pragma unroll
    for (int i = 0; i < 4; i++)
#pragma unroll
        for (int j = 0; j < 4; j++) acc[i][j] = 0.f;

    int lrow = tid >> 2;
    int lcol = (tid & 3) * 4;

    for (int k0 = 0; k0 < IN_DIM; k0 += 16) {
        {
            int m = m0 + lrow;
            float4 v = make_float4(0.f, 0.f, 0.f, 0.f);
            if (m < M) v = *(const float4*)(A + (long)m * IN_DIM + k0 + lcol);
            As[lcol + 0][lrow] = v.x; As[lcol + 1][lrow] = v.y;
            As[lcol + 2][lrow] = v.z; As[lcol + 3][lrow] = v.w;
        }
        {
            int n = n0 + lrow;
            float4 v = *(const float4*)(Bw + (long)n * IN_DIM + k0 + lcol);
            Bs[lcol + 0][lrow] = v.x; Bs[lcol + 1][lrow] = v.y;
            Bs[lcol + 2][lrow] = v.z; Bs[lcol + 3][lrow] = v.w;
        }
        __syncthreads();
#pragma unroll
        for (int kk = 0; kk < 16; kk++) {
            float a[4], b[4];
#pragma unroll
            for (int i = 0; i < 4; i++) a[i] = As[kk][ty * 4 + i];
#pragma unroll
            for (int j = 0; j < 4; j++) b[j] = Bs[kk][tx * 4 + j];
#pragma unroll
            for (int i = 0; i < 4; i++)
#pragma unroll
                for (int j = 0; j < 4; j++) acc[i][j] += a[i] * b[j];
        }
        __syncthreads();
    }

#pragma unroll
    for (int i = 0; i < 4; i++) {
#pragma unroll
        for (int j = 0; j < 4; j++) {
            int m = m0 + ty * 4 + i;
            int n = n0 + tx * 4 + j;
            if (m < M) {
                float v = acc[i][j] + bias[n];
                int hh = n >> 6;
                C[(long)hh * headM * 64 + (long)m * 64 + (n & 63)] = v;
            }
        }
    }
}

// ---------------- fused flash attention (online softmax) ----------------
// TI=64 query rows per CTA, 6 j-tiles of 64. 256 threads: tx(col grp), ty(row grp).
// logits[i,j] = (q_i.k_j + QPK[i, j-i+383] + KPQ[j, j-i+383]) * SCALE + maskAdd[j]
#define TI 64
#define SW4(row, d4) (((row) << 4) + ((d4) ^ (((row) >> 2) & 15)))
// smem: sQ4 1024 f4 | sK4 1024 f4 | sV4 1024 f4 | sPB 64*65 f | sMaskF 384 f
#define ATT_SMEM_BYTES (3072 * 16 + (64 * 65 + SS) * 4)   // 67328

__global__ __launch_bounds__(256)
void attn_kernel(const float* __restrict__ Q, const float* __restrict__ K,
                 const float* __restrict__ V,
                 const float* __restrict__ QPK, const float* __restrict__ KPQ,
                 const int* __restrict__ mask, float* __restrict__ vals)
{
    extern __shared__ float4 sm4[];
    float4* sQ4 = sm4;
    float4* sK4 = sm4 + 1024;
    float4* sV4 = sm4 + 2048;
    float*  sPB = (float*)(sm4 + 3072);   // 64*65, time-shared p2c / P
    float*  sMaskF = sPB + 64 * 65;       // 384

    int i0  = blockIdx.x * TI;
    int h   = blockIdx.y;
    int b   = blockIdx.z;
    int tid = threadIdx.x;
    int tx = tid & 15, ty = tid >> 4;
    int r0 = ty * 4, c0 = tx * 4;

    long baseRow = (long)h * BSROWS + (long)b * SS;

    // load Q tile (64x64) swizzled + mask addend
    {
        const float4* Qg = (const float4*)(Q + (baseRow + i0) * DD);
        for (int idx = tid; idx < TI * 16; idx += 256) {
            int r = idx >> 4, d4 = idx & 15;
            sQ4[SW4(r, d4)] = Qg[idx];
        }
        for (int j = tid; j < SS; j += 256)
            sMaskF[j] = (mask[b * SS + j] == 0) ? -9.0e15f : 0.f;
    }

    float out[4][4];
    float mrun[4], runsum[4];
#pragma unroll
    for (int i = 0; i < 4; i++) {
        mrun[i] = -INFINITY; runsum[i] = 0.f;
#pragma unroll
        for (int c = 0; c < 4; c++) out[i][c] = 0.f;
    }

    for (int jt = 0; jt < SS / 64; jt++) {
        int j0 = jt * 64;
        __syncthreads();   // prior tile fully consumed
        {
            const float4* Kg = (const float4*)(K + (baseRow + j0) * DD);
            const float4* Vg = (const float4*)(V + (baseRow + j0) * DD);
            for (int idx = tid; idx < 64 * 16; idx += 256) {
                int r = idx >> 4, d4 = idx & 15;
                sK4[SW4(r, d4)] = Kg[idx];
                sV4[SW4(r, d4)] = Vg[idx];
            }
            // stage p2c: sPB[jj*65 + ii] = KPQ[j0+jj][ (j0+jj) - (i0+ii) + 383 ]
            for (int idx = tid; idx < 64 * 64; idx += 256) {
                int jj = idx >> 6, ii = idx & 63;
                int j = j0 + jj;
                sPB[jj * 65 + ii] = KPQ[(baseRow + j) * LDT + (j - (i0 + ii) + 383)];
            }
        }
        __syncthreads();

        // ---- QK 64x64 tile, 4x4 per thread ----
        float l[4][4];
#pragma unroll
        for (int i = 0; i < 4; i++)
#pragma unroll
            for (int c = 0; c < 4; c++) l[i][c] = 0.f;

#pragma unroll 4
        for (int d4 = 0; d4 < 16; d4++) {
            float4 a[4], bb[4];
#pragma unroll
            for (int i = 0; i < 4; i++) a[i]  = sQ4[SW4(r0 + i, d4)];
#pragma unroll
            for (int c = 0; c < 4; c++) bb[c] = sK4[SW4(c0 + c, d4)];
#pragma unroll
            for (int i = 0; i < 4; i++)
#pragma unroll
                for (int c = 0; c < 4; c++)
                    l[i][c] += a[i].x*bb[c].x + a[i].y*bb[c].y
                             + a[i].z*bb[c].z + a[i].w*bb[c].w;
        }

        // ---- add c2p (global) + p2c (staged), scale, mask ----
#pragma unroll
        for (int i = 0; i < 4; i++) {
            int gi = i0 + r0 + i;
            const float* qpkRow = QPK + (baseRow + gi) * LDT + 383 - gi;
#pragma unroll
            for (int c = 0; c < 4; c++) {
                int j = j0 + c0 + c;
                l[i][c] = (l[i][c] + qpkRow[j] + sPB[(c0 + c) * 65 + (r0 + i)]) * SCALE_F
                          + sMaskF[j];
            }
        }
        __syncthreads();   // all p2c reads done before sPB reused as P

        // ---- online softmax stats via 16-lane half-warp shuffles ----
        float tm[4];
#pragma unroll
        for (int i = 0; i < 4; i++) {
            tm[i] = fmaxf(fmaxf(l[i][0], l[i][1]), fmaxf(l[i][2], l[i][3]));
#pragma unroll
            for (int o = 1; o < 16; o <<= 1)
                tm[i] = fmaxf(tm[i], __shfl_xor_sync(0xffffffffu, tm[i], o));
        }
        float ps[4];
#pragma unroll
        for (int i = 0; i < 4; i++) {
            float newm = fmaxf(mrun[i], tm[i]);
            float f = __expf(mrun[i] - newm);     // first tile: exp(-inf)=0
            mrun[i] = newm;
            runsum[i] *= f;
#pragma unroll
            for (int c = 0; c < 4; c++) out[i][c] *= f;
            float s = 0.f;
#pragma unroll
            for (int c = 0; c < 4; c++) {
                float p = __expf(l[i][c] - newm);
                sPB[(r0 + i) * 65 + (c0 + c)] = p;
                s += p;
            }
            ps[i] = s;
        }
#pragma unroll
        for (int i = 0; i < 4; i++) {
#pragma unroll
            for (int o = 1; o < 16; o <<= 1)
                ps[i] += __shfl_xor_sync(0xffffffffu, ps[i], o);
            runsum[i] += ps[i];
        }
        __syncthreads();   // P tile visible to all

        // ---- PV: out[i][d] += P[i][jj] * V[jj][d] ----
#pragma unroll 4
        for (int jj = 0; jj < 64; jj++) {
            float4 vv = sV4[SW4(jj, tx)];
            float p0 = sPB[(r0 + 0) * 65 + jj];
            float p1 = sPB[(r0 + 1) * 65 + jj];
            float p2 = sPB[(r0 + 2) * 65 + jj];
            float p3 = sPB[(r0 + 3) * 65 + jj];
            out[0][0] += p0*vv.x; out[0][1] += p0*vv.y; out[0][2] += p0*vv.z; out[0][3] += p0*vv.w;
            out[1][0] += p1*vv.x; out[1][1] += p1*vv.y; out[1][2] += p1*vv.z; out[1][3] += p1*vv.w;
            out[2][0] += p2*vv.x; out[2][1] += p2*vv.y; out[2][2] += p2*vv.z; out[2][3] += p2*vv.w;
            out[3][0] += p3*vv.x; out[3][1] += p3*vv.y; out[3][2] += p3*vv.z; out[3][3] += p3*vv.w;
        }
    }

    // ---- normalize + store ----
#pragma unroll
    for (int i = 0; i < 4; i++) {
        float inv = 1.f / runsum[i];
        float4 st = make_float4(out[i][0]*inv, out[i][1]*inv, out[i][2]*inv, out[i][3]*inv);
        *(float4*)(vals + ((long)(b * SS + i0 + r0 + i)) * EE + h * DD + c0) = st;
    }
}

// ---------------- launch ----------------
extern "C" void kernel_launch(void* const* d_in, const int* in_sizes, int n_in,
                              void* d_out, int out_size)
{
    const float* x    = (const float*)d_in[0];
    const int*   mask = (const int*)  d_in[1];
    const float* Wq   = (const float*)d_in[2];
    const float* bq   = (const float*)d_in[3];
    const float* Wk   = (const float*)d_in[4];
    const float* bk   = (const float*)d_in[5];
    const float* Wv   = (const float*)d_in[6];
    const float* bv   = (const float*)d_in[7];
    const float* relt = (const float*)d_in[8];
    const float* Wpk  = (const float*)d_in[9];
    const float* bpk  = (const float*)d_in[10];
    const float* Wpq  = (const float*)d_in[11];
    const float* bpq  = (const float*)d_in[12];
    const float* Wo   = (const float*)d_in[13];
    const float* bo   = (const float*)d_in[14];
    float* out = (float*)d_out;

    float *Q, *K, *V, *PK, *PQ, *QPK, *KPQ, *VALS;
    cudaGetSymbolAddress((void**)&Q,   g_Q);
    cudaGetSymbolAddress((void**)&K,   g_K);
    cudaGetSymbolAddress((void**)&V,   g_V);
    cudaGetSymbolAddress((void**)&PK,  g_PK);
    cudaGetSymbolAddress((void**)&PQ,  g_PQ);
    cudaGetSymbolAddress((void**)&QPK, g_QPK);
    cudaGetSymbolAddress((void**)&KPQ, g_KPQ);
    cudaGetSymbolAddress((void**)&VALS, g_vals);

    dim3 blk(256);

    // merged QKV + positional table projections
    proj_all<<<dim3(1344), blk>>>(x, relt, Wq, bq, Wk, bk, Wv, bv,
                                  Wpk, bpk, Wpq, bpq, Q, K, V, PK, PQ);

    // merged per-head QPK/KPQ GEMMs (band-skipped)
    pos_gemm<<<dim3(12, 48, 16), blk>>>(Q, K, PK, PQ, QPK, KPQ);

    // fused flash attention
    cudaFuncSetAttribute(attn_kernel, cudaFuncAttributeMaxDynamicSharedMemorySize,
                         ATT_SMEM_BYTES);
    attn_kernel<<<dim3(SS / TI, HH, BB), blk, ATT_SMEM_BYTES>>>(
        Q, K, V, QPK, KPQ, mask, VALS);

    // output projection
    gemm_nt<<<dim3(8, 48, 1), blk>>>(VALS, EE, Wo, EE, bo, out, IN_DIM,
                                     BSROWS, IN_DIM, EE);
}

// round 7
// speedup vs baseline: 1.8661x; 1.1736x over previous
#include <cuda_runtime.h>
#include <math.h>

// ---------------- problem constants ----------------
#define BB 8
#define SS 384
#define IN_DIM 512
#define EE 512
#define HH 8
#define DD 64
#define BSROWS (BB*SS)        // 3072
#define ND 767                // distinct rel offsets used: j-i+383 in [0,766]
#define LDT 768               // padded leading dim for QPK/KPQ
#define REL_OFF 128           // rel_table row offset: table row = t + 128
#define SCALE_F 0.07216878364870323f   // 1/sqrt(64*3)

#define LDS_PAD 68            // 68 floats = 272 B, 16B-aligned rows -> LDS.128

// ---------------- scratch (__device__ globals) ------
__device__ float g_Q[(size_t)HH*BSROWS*DD];
__device__ float g_K[(size_t)HH*BSROWS*DD];
__device__ float g_V[(size_t)HH*BSROWS*DD];
__device__ float g_PK[(size_t)HH*ND*DD];
__device__ float g_PQ[(size_t)HH*ND*DD];
__device__ float g_QPK[(size_t)HH*BSROWS*LDT];
__device__ float g_KPQ[(size_t)HH*BSROWS*LDT];
__device__ float g_vals[(size_t)BSROWS*EE];

// ---- shared 64x64x16 tile kernel body (vectorized LDS.128 inner loop) ----
#define GEMM_TILE_BODY(A_EXPR_OK, B_EXPR_OK, KDIM)                              \
    __shared__ float As[16][LDS_PAD];                                           \
    __shared__ float Bs[16][LDS_PAD];                                           \
    int tid = threadIdx.x;                                                      \
    int tx = tid & 15, ty = tid >> 4;                                           \
    float acc[4][4];                                                            \
    _Pragma("unroll")                                                           \
    for (int i = 0; i < 4; i++)                                                 \
        _Pragma("unroll")                                                       \
        for (int j = 0; j < 4; j++) acc[i][j] = 0.f;                            \
    int lrow = tid >> 2;                                                        \
    int lcol = (tid & 3) * 4;                                                   \
    for (int k0 = 0; k0 < (KDIM); k0 += 16) {                                   \
        {                                                                       \
            float4 v = A_EXPR_OK;                                               \
            As[lcol + 0][lrow] = v.x; As[lcol + 1][lrow] = v.y;                 \
            As[lcol + 2][lrow] = v.z; As[lcol + 3][lrow] = v.w;                 \
        }                                                                       \
        {                                                                       \
            float4 v = B_EXPR_OK;                                               \
            Bs[lcol + 0][lrow] = v.x; Bs[lcol + 1][lrow] = v.y;                 \
            Bs[lcol + 2][lrow] = v.z; Bs[lcol + 3][lrow] = v.w;                 \
        }                                                                       \
        __syncthreads();                                                        \
        _Pragma("unroll")                                                       \
        for (int kk = 0; kk < 16; kk++) {                                       \
            float4 a4 = *reinterpret_cast<const float4*>(&As[kk][ty * 4]);      \
            float4 b4 = *reinterpret_cast<const float4*>(&Bs[kk][tx * 4]);      \
            acc[0][0] += a4.x*b4.x; acc[0][1] += a4.x*b4.y;                     \
            acc[0][2] += a4.x*b4.z; acc[0][3] += a4.x*b4.w;                     \
            acc[1][0] += a4.y*b4.x; acc[1][1] += a4.y*b4.y;                     \
            acc[1][2] += a4.y*b4.z; acc[1][3] += a4.y*b4.w;                     \
            acc[2][0] += a4.z*b4.x; acc[2][1] += a4.z*b4.y;                     \
            acc[2][2] += a4.z*b4.z; acc[2][3] += a4.z*b4.w;                     \
            acc[3][0] += a4.w*b4.x; acc[3][1] += a4.w*b4.y;                     \
            acc[3][2] += a4.w*b4.z; acc[3][3] += a4.w*b4.w;                     \
        }                                                                       \
        __syncthreads();                                                        \
    }

// ---------------- output projection GEMM: C = A * B^T + bias -------------
__global__ __launch_bounds__(256)
void gemm_nt(const float* __restrict__ A, int lda,
             const float* __restrict__ Bm, int ldb,
             const float* __restrict__ bias,
             float* __restrict__ C, int ldc,
             int M, int N, int K)
{
    int m0 = blockIdx.y * 64;
    int n0 = blockIdx.x * 64;

    GEMM_TILE_BODY(
        *(const float4*)(A  + (long)(m0 + lrow) * lda + k0 + lcol),
        *(const float4*)(Bm + (long)(n0 + lrow) * ldb + k0 + lcol),
        K)

#pragma unroll
    for (int i = 0; i < 4; i++) {
#pragma unroll
        for (int j = 0; j < 4; j++) {
            int m = m0 + ty * 4 + i;
            int n = n0 + tx * 4 + j;
            C[(long)m * ldc + n] = acc[i][j] + bias[n];
        }
    }
}

// ------------- merged positional GEMM: QPK (z<8) and KPQ (z>=8) ----------
__global__ __launch_bounds__(256)
void pos_gemm(const float* __restrict__ Qm, const float* __restrict__ Km,
              const float* __restrict__ PKm, const float* __restrict__ PQm,
              float* __restrict__ QPKo, float* __restrict__ KPQo)
{
    int m0 = blockIdx.y * 64;
    int n0 = blockIdx.x * 64;
    int z  = blockIdx.z;

    const float *A, *Bm; float* C; int band;
    if (z < 8) {
        A = Qm + (long)z * BSROWS * DD; Bm = PKm + (long)z * ND * DD;
        C = QPKo + (long)z * BSROWS * LDT; band = 1;
    } else {
        int h = z - 8;
        A = Km + (long)h * BSROWS * DD; Bm = PQm + (long)h * ND * DD;
        C = KPQo + (long)h * BSROWS * LDT; band = 2;
    }

    int s0 = m0 % SS;
    if (band == 1) {            // QPK: t needed in [320-s0, 766-s0]
        if (n0 + 63 < 320 - s0 || n0 > 766 - s0) return;
    } else {                    // KPQ: t needed in [s0, s0+446]
        if (n0 + 63 < s0 || n0 > s0 + 446) return;
    }

    GEMM_TILE_BODY(
        *(const float4*)(A + (long)(m0 + lrow) * DD + k0 + lcol),
        ((n0 + lrow) < ND ? *(const float4*)(Bm + (long)(n0 + lrow) * DD + k0 + lcol)
                          : make_float4(0.f, 0.f, 0.f, 0.f)),
        DD)

#pragma unroll
    for (int i = 0; i < 4; i++) {
#pragma unroll
        for (int j = 0; j < 4; j++) {
            int m = m0 + ty * 4 + i;
            int n = n0 + tx * 4 + j;
            if (n < ND)
                C[(long)m * LDT + n] = acc[i][j];
        }
    }
}

// ------------- merged projection kernel: Q,K,V,PK,PQ in one launch --------
__global__ __launch_bounds__(256)
void proj_all(const float* __restrict__ x, const float* __restrict__ relt,
              const float* __restrict__ Wq, const float* __restrict__ bq,
              const float* __restrict__ Wk, const float* __restrict__ bk,
              const float* __restrict__ Wv, const float* __restrict__ bv,
              const float* __restrict__ Wpk, const float* __restrict__ bpk,
              const float* __restrict__ Wpq, const float* __restrict__ bpq,
              float* __restrict__ Qo, float* __restrict__ Ko, float* __restrict__ Vo,
              float* __restrict__ PKo, float* __restrict__ PQo)
{
    int id = blockIdx.x;
    const float *A, *Bw, *bias; float* C;
    int M, headM, m0, n0;
    if (id < 1152) {
        int op = id / 384, rem = id % 384;
        m0 = (rem >> 3) * 64; n0 = (rem & 7) * 64;
        A = x; M = BSROWS; headM = BSROWS;
        if (op == 0)      { Bw = Wq; bias = bq; C = Qo; }
        else if (op == 1) { Bw = Wk; bias = bk; C = Ko; }
        else              { Bw = Wv; bias = bv; C = Vo; }
    } else {
        int id2 = id - 1152;
        int op = id2 / 96, rem = id2 % 96;
        m0 = (rem >> 3) * 64; n0 = (rem & 7) * 64;
        A = relt + (long)REL_OFF * IN_DIM; M = ND; headM = ND;
        if (op == 0) { Bw = Wpk; bias = bpk; C = PKo; }
        else         { Bw = Wpq; bias = bpq; C = PQo; }
    }

    GEMM_TILE_BODY(
        ((m0 + lrow) < M ? *(const float4*)(A + (long)(m0 + lrow) * IN_DIM + k0 + lcol)
                         : make_float4(0.f, 0.f, 0.f, 0.f)),
        *(const float4*)(Bw + (long)(n0 + lrow) * IN_DIM + k0 + lcol),
        IN_DIM)

#pragma unroll
    for (int i = 0; i < 4; i++) {
#pragma unroll
        for (int j = 0; j < 4; j++) {
            int m = m0 + ty * 4 + i;
            int n = n0 + tx * 4 + j;
            if (m < M) {
                float v = acc[i][j] + bias[n];
                int hh = n >> 6;
                C[(long)hh * headM * 64 + (long)m * 64 + (n & 63)] = v;
            }
        }
    }
}

// ---------------- fused flash attention (online softmax) ----------------
#define TI 64
#define SW4(row, d4) (((row) << 4) + ((d4) ^ (((row) >> 2) & 15)))
#define ATT_SMEM_BYTES (3072 * 16 + (64 * 65 + SS) * 4)   // 67328

__global__ __launch_bounds__(256)
void attn_kernel(const float* __restrict__ Q, const float* __restrict__ K,
                 const float* __restrict__ V,
                 const float* __restrict__ QPK, const float* __restrict__ KPQ,
                 const int* __restrict__ mask, float* __restrict__ vals)
{
    extern __shared__ float4 sm4[];
    float4* sQ4 = sm4;
    float4* sK4 = sm4 + 1024;
    float4* sV4 = sm4 + 2048;
    float*  sPB = (float*)(sm4 + 3072);   // 64*65, time-shared p2c / P
    float*  sMaskF = sPB + 64 * 65;       // 384

    int i0  = blockIdx.x * TI;
    int h   = blockIdx.y;
    int b   = blockIdx.z;
    int tid = threadIdx.x;
    int tx = tid & 15, ty = tid >> 4;
    int r0 = ty * 4, c0 = tx * 4;

    long baseRow = (long)h * BSROWS + (long)b * SS;

    {
        const float4* Qg = (const float4*)(Q + (baseRow + i0) * DD);
        for (int idx = tid; idx < TI * 16; idx += 256) {
            int r = idx >> 4, d4 = idx & 15;
            sQ4[SW4(r, d4)] = Qg[idx];
        }
        for (int j = tid; j < SS; j += 256)
            sMaskF[j] = (mask[b * SS + j] == 0) ? -9.0e15f : 0.f;
    }

    float out[4][4];
    float mrun[4], runsum[4];
#pragma unroll
    for (int i = 0; i < 4; i++) {
        mrun[i] = -INFINITY; runsum[i] = 0.f;
#pragma unroll
        for (int c = 0; c < 4; c++) out[i][c] = 0.f;
    }

    for (int jt = 0; jt < SS / 64; jt++) {
        int j0 = jt * 64;
        __syncthreads();
        {
            const float4* Kg = (const float4*)(K + (baseRow + j0) * DD);
            const float4* Vg = (const float4*)(V + (baseRow + j0) * DD);
            for (int idx = tid; idx < 64 * 16; idx += 256) {
                int r = idx >> 4, d4 = idx & 15;
                sK4[SW4(r, d4)] = Kg[idx];
                sV4[SW4(r, d4)] = Vg[idx];
            }
            for (int idx = tid; idx < 64 * 64; idx += 256) {
                int jj = idx >> 6, ii = idx & 63;
                int j = j0 + jj;
                sPB[jj * 65 + ii] = KPQ[(baseRow + j) * LDT + (j - (i0 + ii) + 383)];
            }
        }
        __syncthreads();

        float l[4][4];
#pragma unroll
        for (int i = 0; i < 4; i++)
#pragma unroll
            for (int c = 0; c < 4; c++) l[i][c] = 0.f;

#pragma unroll 4
        for (int d4 = 0; d4 < 16; d4++) {
            float4 a[4], bb[4];
#pragma unroll
            for (int i = 0; i < 4; i++) a[i]  = sQ4[SW4(r0 + i, d4)];
#pragma unroll
            for (int c = 0; c < 4; c++) bb[c] = sK4[SW4(c0 + c, d4)];
#pragma unroll
            for (int i = 0; i < 4; i++)
#pragma unroll
                for (int c = 0; c < 4; c++)
                    l[i][c] += a[i].x*bb[c].x + a[i].y*bb[c].y
                             + a[i].z*bb[c].z + a[i].w*bb[c].w;
        }

#pragma unroll
        for (int i = 0; i < 4; i++) {
            int gi = i0 + r0 + i;
            const float* qpkRow = QPK + (baseRow + gi) * LDT + 383 - gi;
#pragma unroll
            for (int c = 0; c < 4; c++) {
                int j = j0 + c0 + c;
                l[i][c] = (l[i][c] + qpkRow[j] + sPB[(c0 + c) * 65 + (r0 + i)]) * SCALE_F
                          + sMaskF[j];
            }
        }
        __syncthreads();

        float tm[4];
#pragma unroll
        for (int i = 0; i < 4; i++) {
            tm[i] = fmaxf(fmaxf(l[i][0], l[i][1]), fmaxf(l[i][2], l[i][3]));
#pragma unroll
            for (int o = 1; o < 16; o <<= 1)
                tm[i] = fmaxf(tm[i], __shfl_xor_sync(0xffffffffu, tm[i], o));
        }
        float ps[4];
#pragma unroll
        for (int i = 0; i < 4; i++) {
            float newm = fmaxf(mrun[i], tm[i]);
            float f = __expf(mrun[i] - newm);
            mrun[i] = newm;
            runsum[i] *= f;
#pragma unroll
            for (int c = 0; c < 4; c++) out[i][c] *= f;
            float s = 0.f;
#pragma unroll
            for (int c = 0; c < 4; c++) {
                float p = __expf(l[i][c] - newm);
                sPB[(r0 + i) * 65 + (c0 + c)] = p;
                s += p;
            }
            ps[i] = s;
        }
#pragma unroll
        for (int i = 0; i < 4; i++) {
#pragma unroll
            for (int o = 1; o < 16; o <<= 1)
                ps[i] += __shfl_xor_sync(0xffffffffu, ps[i], o);
            runsum[i] += ps[i];
        }
        __syncthreads();

#pragma unroll 4
        for (int jj = 0; jj < 64; jj++) {
            float4 vv = sV4[SW4(jj, tx)];
            float p0 = sPB[(r0 + 0) * 65 + jj];
            float p1 = sPB[(r0 + 1) * 65 + jj];
            float p2 = sPB[(r0 + 2) * 65 + jj];
            float p3 = sPB[(r0 + 3) * 65 + jj];
            out[0][0] += p0*vv.x; out[0][1] += p0*vv.y; out[0][2] += p0*vv.z; out[0][3] += p0*vv.w;
            out[1][0] += p1*vv.x; out[1][1] += p1*vv.y; out[1][2] += p1*vv.z; out[1][3] += p1*vv.w;
            out[2][0] += p2*vv.x; out[2][1] += p2*vv.y; out[2][2] += p2*vv.z; out[2][3] += p2*vv.w;
            out[3][0] += p3*vv.x; out[3][1] += p3*vv.y; out[3][2] += p3*vv.z; out[3][3] += p3*vv.w;
        }
    }

#pragma unroll
    for (int i = 0; i < 4; i++) {
        float inv = 1.f / runsum[i];
        float4 st = make_float4(out[i][0]*inv, out[i][1]*inv, out[i][2]*inv, out[i][3]*inv);
        *(float4*)(vals + ((long)(b * SS + i0 + r0 + i)) * EE + h * DD + c0) = st;
    }
}

// ---------------- launch ----------------
extern "C" void kernel_launch(void* const* d_in, const int* in_sizes, int n_in,
                              void* d_out, int out_size)
{
    const float* x    = (const float*)d_in[0];
    const int*   mask = (const int*)  d_in[1];
    const float* Wq   = (const float*)d_in[2];
    const float* bq   = (const float*)d_in[3];
    const float* Wk   = (const float*)d_in[4];
    const float* bk   = (const float*)d_in[5];
    const float* Wv   = (const float*)d_in[6];
    const float* bv   = (const float*)d_in[7];
    const float* relt = (const float*)d_in[8];
    const float* Wpk  = (const float*)d_in[9];
    const float* bpk  = (const float*)d_in[10];
    const float* Wpq  = (const float*)d_in[11];
    const float* bpq  = (const float*)d_in[12];
    const float* Wo   = (const float*)d_in[13];
    const float* bo   = (const float*)d_in[14];
    float* out = (float*)d_out;

    float *Q, *K, *V, *PK, *PQ, *QPK, *KPQ, *VALS;
    cudaGetSymbolAddress((void**)&Q,   g_Q);
    cudaGetSymbolAddress((void**)&K,   g_K);
    cudaGetSymbolAddress((void**)&V,   g_V);
    cudaGetSymbolAddress((void**)&PK,  g_PK);
    cudaGetSymbolAddress((void**)&PQ,  g_PQ);
    cudaGetSymbolAddress((void**)&QPK, g_QPK);
    cudaGetSymbolAddress((void**)&KPQ, g_KPQ);
    cudaGetSymbolAddress((void**)&VALS, g_vals);

    dim3 blk(256);

    // merged QKV + positional table projections
    proj_all<<<dim3(1344), blk>>>(x, relt, Wq, bq, Wk, bk, Wv, bv,
                                  Wpk, bpk, Wpq, bpq, Q, K, V, PK, PQ);

    // merged per-head QPK/KPQ GEMMs (band-skipped)
    pos_gemm<<<dim3(12, 48, 16), blk>>>(Q, K, PK, PQ, QPK, KPQ);

    // fused flash attention
    cudaFuncSetAttribute(attn_kernel, cudaFuncAttributeMaxDynamicSharedMemorySize,
                         ATT_SMEM_BYTES);
    attn_kernel<<<dim3(SS / TI, HH, BB), blk, ATT_SMEM_BYTES>>>(
        Q, K, V, QPK, KPQ, mask, VALS);

    // output projection
    gemm_nt<<<dim3(8, 48, 1), blk>>>(VALS, EE, Wo, EE, bo, out, IN_DIM,
                                     BSROWS, IN_DIM, EE);
}

// round 8
// speedup vs baseline: 2.3697x; 1.2699x over previous
#include <cuda_runtime.h>
#include <math.h>
#include <stdint.h>

// ---------------- problem constants ----------------
#define BB 8
#define SS 384
#define IN_DIM 512
#define EE 512
#define HH 8
#define DD 64
#define BSROWS (BB*SS)        // 3072
#define ND 767                // distinct rel offsets used: j-i+383 in [0,766]
#define LDT 768               // padded leading dim for QPK/KPQ
#define REL_OFF 128           // rel_table row offset: table row = t + 128
#define SCALE_F 0.07216878364870323f   // 1/sqrt(64*3)

// ---------------- scratch (__device__ globals) ------
__device__ float g_Q[(size_t)HH*BSROWS*DD];
__device__ float g_K[(size_t)HH*BSROWS*DD];
__device__ float g_V[(size_t)HH*BSROWS*DD];
__device__ float g_PK[(size_t)HH*ND*DD];
__device__ float g_PQ[(size_t)HH*ND*DD];
__device__ float g_QPK[(size_t)HH*BSROWS*LDT];
__device__ float g_KPQ[(size_t)HH*BSROWS*LDT];
__device__ float g_vals[(size_t)BSROWS*EE];

// =================== tf32 tensor-core tile machinery =====================
// Block tile 128(M) x 128(N), K-step 32, 256 threads.
// 8 warps: wm = wid>>2 (0..1) over M 64 each, wn = wid&3 (0..3) over N 32 each.
// Warp tile 64x32 = 4 m16 atoms x 4 n8 atoms of mma.m16n8k8.tf32.
#define SM_PAD 36   // row stride in 32-bit words; 9r mod 8 cycles banks -> conflict-free

__device__ __forceinline__ uint32_t f2tf(float x) {
    uint32_t u;
    asm("cvt.rna.tf32.f32 %0, %1;" : "=r"(u) : "f"(x));
    return u;
}

__device__ __forceinline__ void mma_tf32(float* d, const uint32_t* a, const uint32_t* b) {
    asm volatile(
        "mma.sync.aligned.m16n8k8.row.col.f32.tf32.tf32.f32 "
        "{%0,%1,%2,%3}, {%4,%5,%6,%7}, {%8,%9}, {%0,%1,%2,%3};\n"
        : "+f"(d[0]), "+f"(d[1]), "+f"(d[2]), "+f"(d[3])
        : "r"(a[0]), "r"(a[1]), "r"(a[2]), "r"(a[3]),
          "r"(b[0]), "r"(b[1]));
}

// A: (arows x K) row-major at Aptr (already offset to tile's first row)
// B: (brows x K) row-major at Bptr (already offset to tile's first row)
// acc[am][an][4] accumulates C_tile = A * B^T.
__device__ __forceinline__ void tc_tile(
    const float* __restrict__ A, int lda, int arows,
    const float* __restrict__ B, int ldb, int brows,
    int K, uint32_t* sA, uint32_t* sB, float acc[4][4][4])
{
    int tid  = threadIdx.x;
    int lane = tid & 31;
    int wid  = tid >> 5;
    int wm = wid >> 2, wn = wid & 3;
    int lrow = tid & 127;
    int kb   = (tid >> 7) * 16;
    bool aok = lrow < arows;
    bool bok = lrow < brows;

    for (int k0 = 0; k0 < K; k0 += 32) {
#pragma unroll
        for (int g = 0; g < 4; g++) {
            float4 va = aok ? *(const float4*)(A + (long)lrow * lda + k0 + kb + g * 4)
                            : make_float4(0.f, 0.f, 0.f, 0.f);
            uint4 ua = make_uint4(f2tf(va.x), f2tf(va.y), f2tf(va.z), f2tf(va.w));
            *(uint4*)&sA[lrow * SM_PAD + kb + g * 4] = ua;
            float4 vb = bok ? *(const float4*)(B + (long)lrow * ldb + k0 + kb + g * 4)
                            : make_float4(0.f, 0.f, 0.f, 0.f);
            uint4 ub = make_uint4(f2tf(vb.x), f2tf(vb.y), f2tf(vb.z), f2tf(vb.w));
            *(uint4*)&sB[lrow * SM_PAD + kb + g * 4] = ub;
        }
        __syncthreads();

#pragma unroll
        for (int k8 = 0; k8 < 4; k8++) {
            int c  = k8 * 8 + (lane & 3);
            int rr = lane >> 2;
            uint32_t af[4][4], bf[4][2];
#pragma unroll
            for (int am = 0; am < 4; am++) {
                int r = wm * 64 + am * 16 + rr;
                af[am][0] = sA[r * SM_PAD + c];
                af[am][1] = sA[(r + 8) * SM_PAD + c];
                af[am][2] = sA[r * SM_PAD + c + 4];
                af[am][3] = sA[(r + 8) * SM_PAD + c + 4];
            }
#pragma unroll
            for (int an = 0; an < 4; an++) {
                int n = wn * 32 + an * 8 + rr;
                bf[an][0] = sB[n * SM_PAD + c];
                bf[an][1] = sB[n * SM_PAD + c + 4];
            }
#pragma unroll
            for (int am = 0; am < 4; am++)
#pragma unroll
                for (int an = 0; an < 4; an++)
                    mma_tf32(acc[am][an], af[am], bf[an]);
        }
        __syncthreads();
    }
}

#define TC_PROLOG()                                                            \
    __shared__ uint32_t sA[128 * SM_PAD];                                      \
    __shared__ uint32_t sB[128 * SM_PAD];                                      \
    float acc[4][4][4];                                                        \
    _Pragma("unroll")                                                          \
    for (int i = 0; i < 4; i++)                                                \
        _Pragma("unroll")                                                      \
        for (int j = 0; j < 4; j++)                                            \
            _Pragma("unroll")                                                  \
            for (int r = 0; r < 4; r++) acc[i][j][r] = 0.f;                    \
    int lane = threadIdx.x & 31;                                               \
    int wid  = threadIdx.x >> 5;                                               \
    int wm = wid >> 2, wn = wid & 3;                                           \
    int rr = lane >> 2, cc2 = (lane & 3) * 2;

// ------------- merged projection kernel: Q,K,V,PK,PQ (tf32 TC) ------------
// grid.x = 336: [0,288) QKV (3 ops x 24 m x 4 n), [288,336) PK/PQ (2 x 6 x 4)
__global__ __launch_bounds__(256, 2)
void proj_all_tc(const float* __restrict__ x, const float* __restrict__ relt,
                 const float* __restrict__ Wq, const float* __restrict__ bq,
                 const float* __restrict__ Wk, const float* __restrict__ bk,
                 const float* __restrict__ Wv, const float* __restrict__ bv,
                 const float* __restrict__ Wpk, const float* __restrict__ bpk,
                 const float* __restrict__ Wpq, const float* __restrict__ bpq,
                 float* __restrict__ Qo, float* __restrict__ Ko, float* __restrict__ Vo,
                 float* __restrict__ PKo, float* __restrict__ PQo)
{
    int id = blockIdx.x;
    const float *A, *Bw, *bias; float* C;
    int M, headM, m0, n0;
    if (id < 288) {
        int op = id / 96, rem = id % 96;
        m0 = (rem >> 2) * 128; n0 = (rem & 3) * 128;
        A = x; M = BSROWS; headM = BSROWS;
        if (op == 0)      { Bw = Wq; bias = bq; C = Qo; }
        else if (op == 1) { Bw = Wk; bias = bk; C = Ko; }
        else              { Bw = Wv; bias = bv; C = Vo; }
    } else {
        int id2 = id - 288;
        int op = id2 / 24, rem = id2 % 24;
        m0 = (rem >> 2) * 128; n0 = (rem & 3) * 128;
        A = relt + (long)REL_OFF * IN_DIM; M = ND; headM = ND;
        if (op == 0) { Bw = Wpk; bias = bpk; C = PKo; }
        else         { Bw = Wpq; bias = bpq; C = PQo; }
    }

    TC_PROLOG()
    tc_tile(A + (long)m0 * IN_DIM, IN_DIM, M - m0,
            Bw + (long)n0 * IN_DIM, IN_DIM, 128,
            IN_DIM, sA, sB, acc);

#pragma unroll
    for (int am = 0; am < 4; am++) {
#pragma unroll
        for (int p = 0; p < 2; p++) {
            int m = m0 + wm * 64 + am * 16 + rr + p * 8;
            if (m >= M) continue;
#pragma unroll
            for (int an = 0; an < 4; an++) {
#pragma unroll
                for (int q = 0; q < 2; q++) {
                    int n = n0 + wn * 32 + an * 8 + cc2 + q;
                    float v = acc[am][an][p * 2 + q] + bias[n];
                    C[(long)(n >> 6) * headM * 64 + (long)m * 64 + (n & 63)] = v;
                }
            }
        }
    }
}

// ------------- merged positional GEMM: QPK (z<8) / KPQ (z>=8), tf32 TC ----
// grid (6, 24, 16), band-skipped at 128x128 tile granularity.
__global__ __launch_bounds__(256, 2)
void pos_gemm_tc(const float* __restrict__ Qm, const float* __restrict__ Km,
                 const float* __restrict__ PKm, const float* __restrict__ PQm,
                 float* __restrict__ QPKo, float* __restrict__ KPQo)
{
    int n0 = blockIdx.x * 128;
    int m0 = blockIdx.y * 128;
    int z  = blockIdx.z;

    const float *A, *Bm; float* C;
    int s0 = m0 % SS;
    if (z < 8) {
        // QPK: rows i in [s0, s0+127] need t in [256-s0, 766-s0]
        if (n0 + 127 < 256 - s0 || n0 > 766 - s0) return;
        A = Qm + (long)z * BSROWS * DD; Bm = PKm + (long)z * ND * DD;
        C = QPKo + (long)z * BSROWS * LDT;
    } else {
        // KPQ: rows j in [s0, s0+127] need t in [s0, s0+510]
        if (n0 + 127 < s0 || n0 > s0 + 510) return;
        int h = z - 8;
        A = Km + (long)h * BSROWS * DD; Bm = PQm + (long)h * ND * DD;
        C = KPQo + (long)h * BSROWS * LDT;
    }

    TC_PROLOG()
    tc_tile(A + (long)m0 * DD, DD, 128,
            Bm + (long)n0 * DD, DD, ND - n0,
            DD, sA, sB, acc);

#pragma unroll
    for (int am = 0; am < 4; am++) {
#pragma unroll
        for (int p = 0; p < 2; p++) {
            int m = m0 + wm * 64 + am * 16 + rr + p * 8;
#pragma unroll
            for (int an = 0; an < 4; an++) {
#pragma unroll
                for (int q = 0; q < 2; q++) {
                    int n = n0 + wn * 32 + an * 8 + cc2 + q;
                    if (n < ND)
                        C[(long)m * LDT + n] = acc[am][an][p * 2 + q];
                }
            }
        }
    }
}

// ------------- output projection: out = vals @ Wo^T + bo (tf32 TC) --------
__global__ __launch_bounds__(256, 2)
void out_gemm_tc(const float* __restrict__ A, const float* __restrict__ Bw,
                 const float* __restrict__ bias, float* __restrict__ C)
{
    int n0 = blockIdx.x * 128;
    int m0 = blockIdx.y * 128;

    TC_PROLOG()
    tc_tile(A + (long)m0 * EE, EE, 128,
            Bw + (long)n0 * EE, EE, 128,
            EE, sA, sB, acc);

#pragma unroll
    for (int am = 0; am < 4; am++) {
#pragma unroll
        for (int p = 0; p < 2; p++) {
            int m = m0 + wm * 64 + am * 16 + rr + p * 8;
#pragma unroll
            for (int an = 0; an < 4; an++) {
#pragma unroll
                for (int q = 0; q < 2; q++) {
                    int n = n0 + wn * 32 + an * 8 + cc2 + q;
                    C[(long)m * IN_DIM + n] = acc[am][an][p * 2 + q] + bias[n];
                }
            }
        }
    }
}

// ---------------- fused flash attention (online softmax, fp32 SIMT) -------
#define TI 64
#define SW4(row, d4) (((row) << 4) + ((d4) ^ (((row) >> 2) & 15)))
#define ATT_SMEM_BYTES (3072 * 16 + (64 * 65 + SS) * 4)   // 67328

__global__ __launch_bounds__(256)
void attn_kernel(const float* __restrict__ Q, const float* __restrict__ K,
                 const float* __restrict__ V,
                 const float* __restrict__ QPK, const float* __restrict__ KPQ,
                 const int* __restrict__ mask, float* __restrict__ vals)
{
    extern __shared__ float4 sm4[];
    float4* sQ4 = sm4;
    float4* sK4 = sm4 + 1024;
    float4* sV4 = sm4 + 2048;
    float*  sPB = (float*)(sm4 + 3072);   // 64*65, time-shared p2c / P
    float*  sMaskF = sPB + 64 * 65;       // 384

    int i0  = blockIdx.x * TI;
    int h   = blockIdx.y;
    int b   = blockIdx.z;
    int tid = threadIdx.x;
    int tx = tid & 15, ty = tid >> 4;
    int r0 = ty * 4, c0 = tx * 4;

    long baseRow = (long)h * BSROWS + (long)b * SS;

    {
        const float4* Qg = (const float4*)(Q + (baseRow + i0) * DD);
        for (int idx = tid; idx < TI * 16; idx += 256) {
            int r = idx >> 4, d4 = idx & 15;
            sQ4[SW4(r, d4)] = Qg[idx];
        }
        for (int j = tid; j < SS; j += 256)
            sMaskF[j] = (mask[b * SS + j] == 0) ? -9.0e15f : 0.f;
    }

    float out[4][4];
    float mrun[4], runsum[4];
#pragma unroll
    for (int i = 0; i < 4; i++) {
        mrun[i] = -INFINITY; runsum[i] = 0.f;
#pragma unroll
        for (int c = 0; c < 4; c++) out[i][c] = 0.f;
    }

    for (int jt = 0; jt < SS / 64; jt++) {
        int j0 = jt * 64;
        __syncthreads();
        {
            const float4* Kg = (const float4*)(K + (baseRow + j0) * DD);
            const float4* Vg = (const float4*)(V + (baseRow + j0) * DD);
            for (int idx = tid; idx < 64 * 16; idx += 256) {
                int r = idx >> 4, d4 = idx & 15;
                sK4[SW4(r, d4)] = Kg[idx];
                sV4[SW4(r, d4)] = Vg[idx];
            }
            for (int idx = tid; idx < 64 * 64; idx += 256) {
                int jj = idx >> 6, ii = idx & 63;
                int j = j0 + jj;
                sPB[jj * 65 + ii] = KPQ[(baseRow + j) * LDT + (j - (i0 + ii) + 383)];
            }
        }
        __syncthreads();

        float l[4][4];
#pragma unroll
        for (int i = 0; i < 4; i++)
#pragma unroll
            for (int c = 0; c < 4; c++) l[i][c] = 0.f;

#pragma unroll 4
        for (int d4 = 0; d4 < 16; d4++) {
            float4 a[4], bb[4];
#pragma unroll
            for (int i = 0; i < 4; i++) a[i]  = sQ4[SW4(r0 + i, d4)];
#pragma unroll
            for (int c = 0; c < 4; c++) bb[c] = sK4[SW4(c0 + c, d4)];
#pragma unroll
            for (int i = 0; i < 4; i++)
#pragma unroll
                for (int c = 0; c < 4; c++)
                    l[i][c] += a[i].x*bb[c].x + a[i].y*bb[c].y
                             + a[i].z*bb[c].z + a[i].w*bb[c].w;
        }

#pragma unroll
        for (int i = 0; i < 4; i++) {
            int gi = i0 + r0 + i;
            const float* qpkRow = QPK + (baseRow + gi) * LDT + 383 - gi;
#pragma unroll
            for (int c = 0; c < 4; c++) {
                int j = j0 + c0 + c;
                l[i][c] = (l[i][c] + qpkRow[j] + sPB[(c0 + c) * 65 + (r0 + i)]) * SCALE_F
                          + sMaskF[j];
            }
        }
        __syncthreads();

        float tm[4];
#pragma unroll
        for (int i = 0; i < 4; i++) {
            tm[i] = fmaxf(fmaxf(l[i][0], l[i][1]), fmaxf(l[i][2], l[i][3]));
#pragma unroll
            for (int o = 1; o < 16; o <<= 1)
                tm[i] = fmaxf(tm[i], __shfl_xor_sync(0xffffffffu, tm[i], o));
        }
        float ps[4];
#pragma unroll
        for (int i = 0; i < 4; i++) {
            float newm = fmaxf(mrun[i], tm[i]);
            float f = __expf(mrun[i] - newm);
            mrun[i] = newm;
            runsum[i] *= f;
#pragma unroll
            for (int c = 0; c < 4; c++) out[i][c] *= f;
            float s = 0.f;
#pragma unroll
            for (int c = 0; c < 4; c++) {
                float p = __expf(l[i][c] - newm);
                sPB[(r0 + i) * 65 + (c0 + c)] = p;
                s += p;
            }
            ps[i] = s;
        }
#pragma unroll
        for (int i = 0; i < 4; i++) {
#pragma unroll
            for (int o = 1; o < 16; o <<= 1)
                ps[i] += __shfl_xor_sync(0xffffffffu, ps[i], o);
            runsum[i] += ps[i];
        }
        __syncthreads();

#pragma unroll 4
        for (int jj = 0; jj < 64; jj++) {
            float4 vv = sV4[SW4(jj, tx)];
            float p0 = sPB[(r0 + 0) * 65 + jj];
            float p1 = sPB[(r0 + 1) * 65 + jj];
            float p2 = sPB[(r0 + 2) * 65 + jj];
            float p3 = sPB[(r0 + 3) * 65 + jj];
            out[0][0] += p0*vv.x; out[0][1] += p0*vv.y; out[0][2] += p0*vv.z; out[0][3] += p0*vv.w;
            out[1][0] += p1*vv.x; out[1][1] += p1*vv.y; out[1][2] += p1*vv.z; out[1][3] += p1*vv.w;
            out[2][0] += p2*vv.x; out[2][1] += p2*vv.y; out[2][2] += p2*vv.z; out[2][3] += p2*vv.w;
            out[3][0] += p3*vv.x; out[3][1] += p3*vv.y; out[3][2] += p3*vv.z; out[3][3] += p3*vv.w;
        }
    }

#pragma unroll
    for (int i = 0; i < 4; i++) {
        float inv = 1.f / runsum[i];
        float4 st = make_float4(out[i][0]*inv, out[i][1]*inv, out[i][2]*inv, out[i][3]*inv);
        *(float4*)(vals + ((long)(b * SS + i0 + r0 + i)) * EE + h * DD + c0) = st;
    }
}

// ---------------- launch ----------------
extern "C" void kernel_launch(void* const* d_in, const int* in_sizes, int n_in,
                              void* d_out, int out_size)
{
    const float* x    = (const float*)d_in[0];
    const int*   mask = (const int*)  d_in[1];
    const float* Wq   = (const float*)d_in[2];
    const float* bq   = (const float*)d_in[3];
    const float* Wk   = (const float*)d_in[4];
    const float* bk   = (const float*)d_in[5];
    const float* Wv   = (const float*)d_in[6];
    const float* bv   = (const float*)d_in[7];
    const float* relt = (const float*)d_in[8];
    const float* Wpk  = (const float*)d_in[9];
    const float* bpk  = (const float*)d_in[10];
    const float* Wpq  = (const float*)d_in[11];
    const float* bpq  = (const float*)d_in[12];
    const float* Wo   = (const float*)d_in[13];
    const float* bo   = (const float*)d_in[14];
    float* out = (float*)d_out;

    float *Q, *K, *V, *PK, *PQ, *QPK, *KPQ, *VALS;
    cudaGetSymbolAddress((void**)&Q,   g_Q);
    cudaGetSymbolAddress((void**)&K,   g_K);
    cudaGetSymbolAddress((void**)&V,   g_V);
    cudaGetSymbolAddress((void**)&PK,  g_PK);
    cudaGetSymbolAddress((void**)&PQ,  g_PQ);
    cudaGetSymbolAddress((void**)&QPK, g_QPK);
    cudaGetSymbolAddress((void**)&KPQ, g_KPQ);
    cudaGetSymbolAddress((void**)&VALS, g_vals);

    dim3 blk(256);

    // merged QKV + positional table projections (tf32 tensor cores)
    proj_all_tc<<<dim3(336), blk>>>(x, relt, Wq, bq, Wk, bk, Wv, bv,
                                    Wpk, bpk, Wpq, bpq, Q, K, V, PK, PQ);

    // merged per-head QPK/KPQ GEMMs (tf32 TC, band-skipped)
    pos_gemm_tc<<<dim3(6, 24, 16), blk>>>(Q, K, PK, PQ, QPK, KPQ);

    // fused flash attention (fp32)
    cudaFuncSetAttribute(attn_kernel, cudaFuncAttributeMaxDynamicSharedMemorySize,
                         ATT_SMEM_BYTES);
    attn_kernel<<<dim3(SS / TI, HH, BB), blk, ATT_SMEM_BYTES>>>(
        Q, K, V, QPK, KPQ, mask, VALS);

    // output projection (tf32 TC)
    out_gemm_tc<<<dim3(4, 24), blk>>>(VALS, Wo, bo, out);
}